// round 1
// baseline (speedup 1.0000x reference)
#include <cuda_runtime.h>
#include <math.h>

// Problem-instance max sizes (N=50000, E=800000, E'=850000)
#define NMAX 50000
#define EPMAX 850016

// ---------------- scratch (device globals; no allocation allowed) ----------------
__device__ float g_h[NMAX * 128];      // x @ W_gat
__device__ float g_asrc[NMAX * 4];
__device__ float g_adst[NMAX * 4];
__device__ float g_emax[NMAX * 4];     // segment max per (dst, head)
__device__ float g_esum[NMAX * 4];     // segment exp-sum per (dst, head)
__device__ float g_expw[EPMAX * 4];    // exp(e - max) per edge/head
__device__ float g_acc1[NMAX * 128];   // GAT aggregation -> out1 (in place)
__device__ float g_deg[NMAX];
__device__ float g_dinv[NMAX];
__device__ float g_h2[NMAX * 128];     // out1 @ W_gcn
__device__ float g_out2[NMAX * 128];   // GCN aggregation -> out2 (in place)
__device__ float g_gate[NMAX];
__device__ float g_gmax[64];
__device__ float g_gsum[64];
__device__ float g_gacc[64 * 128];

// ---------------- helpers ----------------
__device__ __forceinline__ float lrelu(float v) { return v > 0.f ? v : 0.2f * v; }
__device__ __forceinline__ float elu_f(float v) { return v > 0.f ? v : (__expf(v) - 1.f); }

__device__ __forceinline__ void atomicMaxF(float* a, float v) {
    if (v >= 0.f) atomicMax((int*)a, __float_as_int(v));
    else          atomicMin((unsigned int*)a, __float_as_uint(v));
}

__device__ __forceinline__ void ffma2(unsigned long long& d, unsigned long long a,
                                      unsigned long long b) {
    asm("fma.rn.f32x2 %0, %1, %2, %0;" : "+l"(d) : "l"(a), "l"(b));
}
__device__ __forceinline__ unsigned long long dup2(float v) {
    unsigned long long r;
    asm("mov.b64 %0, {%1, %1};" : "=l"(r) : "f"(v));
    return r;
}

// ---------------- init ----------------
__global__ void init_kernel(float* acc1, float* out2, float* emax, float* esum,
                            float* deg, float* gmax_, float* gsum, float* gacc, int N) {
    int i = blockIdx.x * blockDim.x + threadIdx.x;
    const float NEG_INF = __int_as_float(0xff800000);
    if (i < N * 128) { acc1[i] = 0.f; out2[i] = 0.f; }
    if (i < N * 4)   { emax[i] = NEG_INF; esum[i] = 0.f; }
    if (i < N)       { deg[i] = 0.f; }
    if (i < 64)      { gmax_[i] = NEG_INF; gsum[i] = 0.f; }
    if (i < 64 * 128){ gacc[i] = 0.f; }
}

// ---------------- GEMM: C[N,128] = A[N,128] @ W[128,128], fp32 via FFMA2 ----------------
__global__ __launch_bounds__(256) void gemm128_kernel(const float* __restrict__ A,
                                                      const float* __restrict__ W,
                                                      float* __restrict__ C, int N) {
    __shared__ float As[32 * 128];   // 16 KB
    __shared__ float Ws[64 * 128];   // 32 KB  (total = 48 KB exactly)
    int t = threadIdx.x;
    int r  = t >> 3;     // row within tile 0..31
    int cg = t & 7;      // column group: cols cg*16 .. +15
    int row0 = blockIdx.x * 32;

    // load A tile [32,128]
    #pragma unroll
    for (int i = t; i < 1024; i += 256) {
        int rr = i >> 5, cc = i & 31;
        float4 v = make_float4(0.f, 0.f, 0.f, 0.f);
        if (row0 + rr < N) v = ((const float4*)A)[(row0 + rr) * 32 + cc];
        ((float4*)As)[i] = v;
    }

    unsigned long long acc[8];
    #pragma unroll
    for (int j = 0; j < 8; j++) acc[j] = 0ull;

    #pragma unroll
    for (int kk = 0; kk < 128; kk += 64) {
        __syncthreads();
        #pragma unroll
        for (int i = t; i < 2048; i += 256)
            ((float4*)Ws)[i] = ((const float4*)W)[kk * 32 + i];
        __syncthreads();

        #pragma unroll 4
        for (int k4 = 0; k4 < 16; k4++) {
            float4 xq = *((const float4*)(As + r * 128 + kk + k4 * 4));
            #pragma unroll
            for (int u = 0; u < 4; u++) {
                float xv = (u == 0) ? xq.x : (u == 1) ? xq.y : (u == 2) ? xq.z : xq.w;
                unsigned long long xv2 = dup2(xv);
                const float* wr = Ws + (k4 * 4 + u) * 128 + cg * 16;
                #pragma unroll
                for (int jj = 0; jj < 4; jj++) {
                    ulonglong2 w2 = *((const ulonglong2*)(wr + jj * 4));
                    ffma2(acc[jj * 2],     xv2, w2.x);
                    ffma2(acc[jj * 2 + 1], xv2, w2.y);
                }
            }
        }
    }

    int row = row0 + r;
    if (row < N) {
        float4* cp = (float4*)(C + row * 128 + cg * 16);
        #pragma unroll
        for (int jj = 0; jj < 4; jj++) {
            float2 lo = *(float2*)&acc[jj * 2];
            float2 hi = *(float2*)&acc[jj * 2 + 1];
            cp[jj] = make_float4(lo.x, lo.y, hi.x, hi.y);
        }
    }
}

// ---------------- attention coefficients a_src/a_dst per (node, head) ----------------
__global__ void attn_kernel(const float* __restrict__ h, const float* __restrict__ att_src,
                            const float* __restrict__ att_dst, float* __restrict__ asrc,
                            float* __restrict__ adst, int N) {
    int i = blockIdx.x * blockDim.x + threadIdx.x;
    if (i >= N * 4) return;
    int hh = i & 3;
    const float4* hp = (const float4*)(h + (i >> 2) * 128 + hh * 32);
    const float4* sp = (const float4*)(att_src + hh * 32);
    const float4* dp = (const float4*)(att_dst + hh * 32);
    float ss = 0.f, dd = 0.f;
    #pragma unroll
    for (int j = 0; j < 8; j++) {
        float4 v = hp[j], a = sp[j], b = dp[j];
        ss += v.x * a.x + v.y * a.y + v.z * a.z + v.w * a.w;
        dd += v.x * b.x + v.y * b.y + v.z * b.z + v.w * b.w;
    }
    asrc[i] = ss;
    adst[i] = dd;
}

// ---------------- edge pass 1: segment max + degree ----------------
__global__ void edge_max_kernel(const int* __restrict__ ei, int E, int EP,
                                const float* __restrict__ asrc, const float* __restrict__ adst,
                                float* emax, float* deg) {
    int e = blockIdx.x * blockDim.x + threadIdx.x;
    if (e >= EP) return;
    int s, d;
    if (e < E) { s = ei[e]; d = ei[E + e]; } else { s = e - E; d = s; }
    float4 as = *(const float4*)(asrc + s * 4);
    float4 ad = *(const float4*)(adst + d * 4);
    atomicMaxF(emax + d * 4 + 0, lrelu(as.x + ad.x));
    atomicMaxF(emax + d * 4 + 1, lrelu(as.y + ad.y));
    atomicMaxF(emax + d * 4 + 2, lrelu(as.z + ad.z));
    atomicMaxF(emax + d * 4 + 3, lrelu(as.w + ad.w));
    atomicAdd(deg + d, 1.f);
}

// ---------------- edge pass 2: exp + segment sum ----------------
__global__ void edge_exp_kernel(const int* __restrict__ ei, int E, int EP,
                                const float* __restrict__ asrc, const float* __restrict__ adst,
                                const float* __restrict__ emax,
                                float* __restrict__ expw, float* esum) {
    int e = blockIdx.x * blockDim.x + threadIdx.x;
    if (e >= EP) return;
    int s, d;
    if (e < E) { s = ei[e]; d = ei[E + e]; } else { s = e - E; d = s; }
    float4 as = *(const float4*)(asrc + s * 4);
    float4 ad = *(const float4*)(adst + d * 4);
    float4 m  = *(const float4*)(emax + d * 4);
    float4 w;
    w.x = __expf(lrelu(as.x + ad.x) - m.x);
    w.y = __expf(lrelu(as.y + ad.y) - m.y);
    w.z = __expf(lrelu(as.z + ad.z) - m.z);
    w.w = __expf(lrelu(as.w + ad.w) - m.w);
    *(float4*)(expw + e * 4) = w;
    atomicAdd((float4*)(esum + d * 4), w);
}

// ---------------- edge pass 3: GAT message aggregation (warp per edge) ----------------
__global__ __launch_bounds__(256) void gat_agg_kernel(const int* __restrict__ ei, int E, int EP,
                                                      const float* __restrict__ h,
                                                      const float* __restrict__ expw,
                                                      const float* __restrict__ esum,
                                                      float* __restrict__ acc) {
    int w = (blockIdx.x * 256 + threadIdx.x) >> 5;
    if (w >= EP) return;
    int lane = threadIdx.x & 31;
    int s, d;
    if (w < E) { s = ei[w]; d = ei[E + w]; } else { s = w - E; d = s; }
    float4 ew = *(const float4*)(expw + w * 4);
    float4 es = *(const float4*)(esum + d * 4);
    float a0 = ew.x / (es.x + 1e-16f);
    float a1 = ew.y / (es.y + 1e-16f);
    float a2 = ew.z / (es.z + 1e-16f);
    float a3 = ew.w / (es.w + 1e-16f);
    float a = (lane < 8) ? a0 : (lane < 16) ? a1 : (lane < 24) ? a2 : a3;  // head = lane/8
    float4 v = *(const float4*)(h + s * 128 + lane * 4);
    float4 m = make_float4(v.x * a, v.y * a, v.z * a, v.w * a);
    atomicAdd((float4*)(acc + d * 128 + lane * 4), m);
}

// ---------------- node post 1: out1 = bn(elu(acc + b_gat)); dinv ----------------
__global__ void node1_kernel(float* acc, const float* __restrict__ b,
                             const float* __restrict__ w1, const float* __restrict__ b1,
                             const float* __restrict__ deg, float* dinv, int N) {
    int i = blockIdx.x * blockDim.x + threadIdx.x;
    if (i >= N * 128) return;
    int c = i & 127;
    float v = acc[i] + b[c];
    v = elu_f(v);
    acc[i] = v * w1[c] + b1[c];
    if (c == 0) {
        int n = i >> 7;
        dinv[n] = rsqrtf(fmaxf(deg[n], 1.f));
    }
}

// ---------------- GCN aggregation (warp per edge) ----------------
__global__ __launch_bounds__(256) void gcn_agg_kernel(const int* __restrict__ ei, int E, int EP,
                                                      const float* __restrict__ h2,
                                                      const float* __restrict__ dinv,
                                                      float* __restrict__ acc) {
    int w = (blockIdx.x * 256 + threadIdx.x) >> 5;
    if (w >= EP) return;
    int lane = threadIdx.x & 31;
    int s, d;
    if (w < E) { s = ei[w]; d = ei[E + w]; } else { s = w - E; d = s; }
    float norm = dinv[s] * dinv[d];
    float4 v = *(const float4*)(h2 + s * 128 + lane * 4);
    float4 m = make_float4(v.x * norm, v.y * norm, v.z * norm, v.w * norm);
    atomicAdd((float4*)(acc + d * 128 + lane * 4), m);
}

// ---------------- node post 2: out2 = bn(elu(acc + b_gcn)); gate; gate max ----------------
__global__ __launch_bounds__(128) void node2_kernel(float* out2, const float* __restrict__ b,
                                                    const float* __restrict__ w2,
                                                    const float* __restrict__ b2,
                                                    const float* __restrict__ W_gate,
                                                    const float* __restrict__ b_gate,
                                                    const int* __restrict__ batch,
                                                    float* gate, float* gmax_, int N) {
    int n = blockIdx.x;
    int c = threadIdx.x;
    float v = out2[n * 128 + c] + b[c];
    v = elu_f(v);
    v = v * w2[c] + b2[c];
    out2[n * 128 + c] = v;
    float p = v * W_gate[c];
    #pragma unroll
    for (int o = 16; o; o >>= 1) p += __shfl_xor_sync(0xffffffffu, p, o);
    __shared__ float sr[4];
    if ((c & 31) == 0) sr[c >> 5] = p;
    __syncthreads();
    if (c == 0) {
        float g = sr[0] + sr[1] + sr[2] + sr[3] + b_gate[0];
        gate[n] = g;
        atomicMaxF(gmax_ + batch[n], g);
    }
}

// ---------------- pooling: accumulate wexp and wexp*out2 ----------------
__global__ __launch_bounds__(128) void pool_kernel(const float* __restrict__ out2,
                                                   const float* __restrict__ gate,
                                                   const float* __restrict__ gmax_,
                                                   const int* __restrict__ batch,
                                                   float* gsum, float* gacc, int N) {
    int n = blockIdx.x;
    int c = threadIdx.x;
    int b = batch[n];
    float wv = __expf(gate[n] - gmax_[b]);
    atomicAdd(gacc + b * 128 + c, wv * out2[n * 128 + c]);
    if (c == 0) atomicAdd(gsum + b, wv);
}

// ---------------- final: out[g] = (gacc/gsum) . W_fc + b_fc ----------------
__global__ __launch_bounds__(128) void final_kernel(const float* __restrict__ gacc,
                                                    const float* __restrict__ gsum,
                                                    const float* __restrict__ W_fc,
                                                    const float* __restrict__ b_fc,
                                                    float* out) {
    int g = blockIdx.x;
    int c = threadIdx.x;
    float v = gacc[g * 128 + c] / (gsum[g] + 1e-16f) * W_fc[c];
    #pragma unroll
    for (int o = 16; o; o >>= 1) v += __shfl_xor_sync(0xffffffffu, v, o);
    __shared__ float sr[4];
    if ((c & 31) == 0) sr[c >> 5] = v;
    __syncthreads();
    if (c == 0) out[g] = sr[0] + sr[1] + sr[2] + sr[3] + b_fc[0];
}

// ---------------- launch ----------------
extern "C" void kernel_launch(void* const* d_in, const int* in_sizes, int n_in,
                              void* d_out, int out_size) {
    const float* x       = (const float*)d_in[0];
    const int*   ei      = (const int*)d_in[1];
    const int*   batch   = (const int*)d_in[2];
    const float* W_gat   = (const float*)d_in[3];
    const float* att_src = (const float*)d_in[4];
    const float* att_dst = (const float*)d_in[5];
    const float* b_gat   = (const float*)d_in[6];
    const float* bn1w    = (const float*)d_in[7];
    const float* bn1b    = (const float*)d_in[8];
    const float* W_gcn   = (const float*)d_in[9];
    const float* b_gcn   = (const float*)d_in[10];
    const float* bn2w    = (const float*)d_in[11];
    const float* bn2b    = (const float*)d_in[12];
    const float* W_gate  = (const float*)d_in[13];
    const float* b_gate  = (const float*)d_in[14];
    const float* W_fc    = (const float*)d_in[15];
    const float* b_fc    = (const float*)d_in[16];
    float* out = (float*)d_out;

    int N  = in_sizes[0] / 128;
    int E  = in_sizes[1] / 2;
    int EP = E + N;

    // resolve scratch addresses (host-side, immediate — capture-safe)
    float *p_h, *p_asrc, *p_adst, *p_emax, *p_esum, *p_expw, *p_acc1, *p_deg, *p_dinv;
    float *p_h2, *p_out2, *p_gate, *p_gmax, *p_gsum, *p_gacc;
    cudaGetSymbolAddress((void**)&p_h,    g_h);
    cudaGetSymbolAddress((void**)&p_asrc, g_asrc);
    cudaGetSymbolAddress((void**)&p_adst, g_adst);
    cudaGetSymbolAddress((void**)&p_emax, g_emax);
    cudaGetSymbolAddress((void**)&p_esum, g_esum);
    cudaGetSymbolAddress((void**)&p_expw, g_expw);
    cudaGetSymbolAddress((void**)&p_acc1, g_acc1);
    cudaGetSymbolAddress((void**)&p_deg,  g_deg);
    cudaGetSymbolAddress((void**)&p_dinv, g_dinv);
    cudaGetSymbolAddress((void**)&p_h2,   g_h2);
    cudaGetSymbolAddress((void**)&p_out2, g_out2);
    cudaGetSymbolAddress((void**)&p_gate, g_gate);
    cudaGetSymbolAddress((void**)&p_gmax, g_gmax);
    cudaGetSymbolAddress((void**)&p_gsum, g_gsum);
    cudaGetSymbolAddress((void**)&p_gacc, g_gacc);

    int nthread_init = N * 128;
    init_kernel<<<(nthread_init + 255) / 256, 256>>>(p_acc1, p_out2, p_emax, p_esum,
                                                     p_deg, p_gmax, p_gsum, p_gacc, N);

    // GAT
    gemm128_kernel<<<(N + 31) / 32, 256>>>(x, W_gat, p_h, N);
    attn_kernel<<<(N * 4 + 255) / 256, 256>>>(p_h, att_src, att_dst, p_asrc, p_adst, N);
    edge_max_kernel<<<(EP + 255) / 256, 256>>>(ei, E, EP, p_asrc, p_adst, p_emax, p_deg);
    edge_exp_kernel<<<(EP + 255) / 256, 256>>>(ei, E, EP, p_asrc, p_adst, p_emax, p_expw, p_esum);
    {
        long long tw = (long long)EP * 32;
        gat_agg_kernel<<<(unsigned)((tw + 255) / 256), 256>>>(ei, E, EP, p_h, p_expw, p_esum, p_acc1);
    }
    node1_kernel<<<(N * 128 + 255) / 256, 256>>>(p_acc1, b_gat, bn1w, bn1b, p_deg, p_dinv, N);

    // GCN
    gemm128_kernel<<<(N + 31) / 32, 256>>>(p_acc1, W_gcn, p_h2, N);
    {
        long long tw = (long long)EP * 32;
        gcn_agg_kernel<<<(unsigned)((tw + 255) / 256), 256>>>(ei, E, EP, p_h2, p_dinv, p_out2);
    }
    node2_kernel<<<N, 128>>>(p_out2, b_gcn, bn2w, bn2b, W_gate, b_gate, batch, p_gate, p_gmax, N);

    // Global attention pooling + FC
    pool_kernel<<<N, 128>>>(p_out2, p_gate, p_gmax, batch, p_gsum, p_gacc, N);
    final_kernel<<<64, 128>>>(p_gacc, p_gsum, W_fc, b_fc, out);
}

// round 2
// speedup vs baseline: 2.1530x; 2.1530x over previous
#include <cuda_runtime.h>
#include <math.h>

#define NMAX 50048
#define EMAX 800000

// ---------------- scratch (device globals) ----------------
__device__ float g_h[NMAX * 128];      // x @ W_gat
__device__ float g_asrc[NMAX * 4];
__device__ float g_adst[NMAX * 4];
__device__ float g_out1[NMAX * 128];   // GAT output (post bn)
__device__ float g_h2[NMAX * 128];     // out1 @ W_gcn
__device__ float g_out2[NMAX * 128];   // GCN output (post bn)
__device__ float g_gate[NMAX];
__device__ float g_dinv[NMAX];
__device__ int   g_cnt[NMAX];
__device__ int   g_offs[NMAX + 1];
__device__ int   g_cursor[NMAX];
__device__ int   g_csr[EMAX];
__device__ int   g_gstart[64];
__device__ int   g_gend[64];

// ---------------- helpers ----------------
__device__ __forceinline__ float lrelu(float v) { return v > 0.f ? v : 0.2f * v; }
__device__ __forceinline__ float elu_f(float v) { return v > 0.f ? v : (__expf(v) - 1.f); }

__device__ __forceinline__ float4 lr4(float4 a) {
    return make_float4(lrelu(a.x), lrelu(a.y), lrelu(a.z), lrelu(a.w));
}
__device__ __forceinline__ float4 add4(float4 a, float4 b) {
    return make_float4(a.x + b.x, a.y + b.y, a.z + b.z, a.w + b.w);
}
__device__ __forceinline__ float4 max4(float4 a, float4 b) {
    return make_float4(fmaxf(a.x, b.x), fmaxf(a.y, b.y), fmaxf(a.z, b.z), fmaxf(a.w, b.w));
}
__device__ __forceinline__ float4 expsub4(float4 a, float4 m) {
    return make_float4(__expf(a.x - m.x), __expf(a.y - m.y), __expf(a.z - m.z), __expf(a.w - m.w));
}
__device__ __forceinline__ float getc(float4 v, int i) {
    return i == 0 ? v.x : i == 1 ? v.y : i == 2 ? v.z : v.w;
}

__device__ __forceinline__ void ffma2(unsigned long long& d, unsigned long long a,
                                      unsigned long long b) {
    asm("fma.rn.f32x2 %0, %1, %2, %0;" : "+l"(d) : "l"(a), "l"(b));
}
__device__ __forceinline__ unsigned long long dup2(float v) {
    unsigned long long r;
    asm("mov.b64 %0, {%1, %1};" : "=l"(r) : "f"(v));
    return r;
}

// ---------------- init: zero edge counters + graph bounds ----------------
__global__ void init_kernel(int* cnt, int* gs, int* ge, int N) {
    int i = blockIdx.x * blockDim.x + threadIdx.x;
    if (i < N) cnt[i] = 0;
    if (i < 64) { gs[i] = 0; ge[i] = 0; }
}

// ---------------- GEMM: C[N,128] = A[N,128] @ W[128,128] ----------------
// 128 rows/block, micro-tile 4 rows x 16 cols per thread, A streamed from global.
__global__ __launch_bounds__(256) void gemm128_kernel(const float* __restrict__ A,
                                                      const float* __restrict__ W,
                                                      float* __restrict__ C, int N) {
    __shared__ float Ws[32 * 128];   // 16 KB chunk of W (32 k-rows)
    int t  = threadIdx.x;
    int cg = t & 7;          // 16-col group
    int rq = t >> 3;         // 0..31, 4 rows each
    int row0 = blockIdx.x * 128 + rq * 4;

    unsigned long long acc[4][8];
    #pragma unroll
    for (int j = 0; j < 4; j++)
        #pragma unroll
        for (int i = 0; i < 8; i++) acc[j][i] = 0ull;

    #pragma unroll
    for (int kk = 0; kk < 128; kk += 32) {
        __syncthreads();
        #pragma unroll
        for (int i = t; i < 1024; i += 256)
            ((float4*)Ws)[i] = ((const float4*)W)[kk * 32 + i];
        __syncthreads();

        #pragma unroll
        for (int k4 = 0; k4 < 8; k4++) {
            float4 a[4];
            #pragma unroll
            for (int j = 0; j < 4; j++) {
                int row = row0 + j;
                a[j] = (row < N) ? ((const float4*)A)[row * 32 + (kk >> 2) + k4]
                                 : make_float4(0.f, 0.f, 0.f, 0.f);
            }
            #pragma unroll
            for (int u = 0; u < 4; u++) {
                const float* wr = Ws + (k4 * 4 + u) * 128 + cg * 16;
                ulonglong2 w0 = *(const ulonglong2*)(wr);
                ulonglong2 w1 = *(const ulonglong2*)(wr + 4);
                ulonglong2 w2 = *(const ulonglong2*)(wr + 8);
                ulonglong2 w3 = *(const ulonglong2*)(wr + 12);
                #pragma unroll
                for (int j = 0; j < 4; j++) {
                    float av = getc(a[j], u);
                    unsigned long long av2 = dup2(av);
                    ffma2(acc[j][0], av2, w0.x); ffma2(acc[j][1], av2, w0.y);
                    ffma2(acc[j][2], av2, w1.x); ffma2(acc[j][3], av2, w1.y);
                    ffma2(acc[j][4], av2, w2.x); ffma2(acc[j][5], av2, w2.y);
                    ffma2(acc[j][6], av2, w3.x); ffma2(acc[j][7], av2, w3.y);
                }
            }
        }
    }

    #pragma unroll
    for (int j = 0; j < 4; j++) {
        int row = row0 + j;
        if (row < N) {
            float4* cp = (float4*)(C + row * 128 + cg * 16);
            #pragma unroll
            for (int m = 0; m < 4; m++) {
                float2 lo = *(float2*)&acc[j][2 * m];
                float2 hi = *(float2*)&acc[j][2 * m + 1];
                cp[m] = make_float4(lo.x, lo.y, hi.x, hi.y);
            }
        }
    }
}

// ---------------- attention coefficients per (node, head) ----------------
__global__ void attn_kernel(const float* __restrict__ h, const float* __restrict__ att_src,
                            const float* __restrict__ att_dst, float* __restrict__ asrc,
                            float* __restrict__ adst, int N) {
    int i = blockIdx.x * blockDim.x + threadIdx.x;
    if (i >= N * 4) return;
    int hh = i & 3;
    const float4* hp = (const float4*)(h + (i >> 2) * 128 + hh * 32);
    const float4* sp = (const float4*)(att_src + hh * 32);
    const float4* dp = (const float4*)(att_dst + hh * 32);
    float ss = 0.f, dd = 0.f;
    #pragma unroll
    for (int j = 0; j < 8; j++) {
        float4 v = hp[j], a = sp[j], b = dp[j];
        ss += v.x * a.x + v.y * a.y + v.z * a.z + v.w * a.w;
        dd += v.x * b.x + v.y * b.y + v.z * b.z + v.w * b.w;
    }
    asrc[i] = ss;
    adst[i] = dd;
}

// ---------------- CSR build ----------------
__global__ void hist_kernel(const int* __restrict__ ei, int E, int* cnt) {
    int e = blockIdx.x * blockDim.x + threadIdx.x;
    if (e >= E) return;
    atomicAdd(cnt + ei[E + e], 1);
}

// single-block exclusive scan over N counts -> offs, cursor
__global__ __launch_bounds__(1024) void scan_kernel(const int* __restrict__ cnt,
                                                    int* offs, int* cursor, int N, int E) {
    __shared__ int ssum[1024];
    int t = threadIdx.x;
    int C = (N + 1023) / 1024;
    int base = t * C;
    int s = 0;
    for (int i = 0; i < C; i++) {
        int idx = base + i;
        if (idx < N) s += cnt[idx];
    }
    ssum[t] = s;
    __syncthreads();
    #pragma unroll
    for (int off = 1; off < 1024; off <<= 1) {
        int v = (t >= off) ? ssum[t - off] : 0;
        __syncthreads();
        ssum[t] += v;
        __syncthreads();
    }
    int running = (t == 0) ? 0 : ssum[t - 1];
    for (int i = 0; i < C; i++) {
        int idx = base + i;
        if (idx < N) {
            offs[idx] = running;
            cursor[idx] = running;
            running += cnt[idx];
        }
    }
    if (t == 0) offs[N] = E;
}

__global__ void scatter_kernel(const int* __restrict__ ei, int E, int* cursor, int* csr) {
    int e = blockIdx.x * blockDim.x + threadIdx.x;
    if (e >= E) return;
    int d = ei[E + e];
    int pos = atomicAdd(cursor + d, 1);
    csr[pos] = ei[e];
}

// ---------------- graph boundaries (batch is sorted) ----------------
__global__ void bounds_kernel(const int* __restrict__ batch, int* gs, int* ge, int N) {
    int n = blockIdx.x * blockDim.x + threadIdx.x;
    if (n >= N) return;
    int b = batch[n];
    if (n == 0 || batch[n - 1] != b) gs[b] = n;
    if (n == N - 1 || batch[n + 1] != b) ge[b] = n + 1;
}

// ---------------- GAT aggregation: warp per node, atomic-free ----------------
__global__ __launch_bounds__(256) void gat_agg_kernel(const int* __restrict__ csr,
                                                      const int* __restrict__ offs,
                                                      const float* __restrict__ h,
                                                      const float* __restrict__ asrc,
                                                      const float* __restrict__ adst,
                                                      const float* __restrict__ b_gat,
                                                      const float* __restrict__ bn1w,
                                                      const float* __restrict__ bn1b,
                                                      float* __restrict__ out1,
                                                      float* __restrict__ dinv, int N) {
    int n = (blockIdx.x * 256 + threadIdx.x) >> 5;
    if (n >= N) return;
    int lane = threadIdx.x & 31;
    int hd = lane >> 3;
    int beg = offs[n], end = offs[n + 1];

    float4 ad = *(const float4*)(adst + n * 4);
    float4 an = *(const float4*)(asrc + n * 4);
    float4 eself = lr4(add4(an, ad));

    // pass 1: per-head max (self loop included)
    float4 m = eself;
    for (int e = beg; e < end; e++) {
        int s = __ldg(csr + e);
        float4 as = *(const float4*)(asrc + s * 4);
        m = max4(m, lr4(add4(as, ad)));
    }

    // pass 2: unnormalized weighted sum + exp-sum
    float4 ws = expsub4(eself, m);
    float4 ssum = ws;
    float aw = getc(ws, hd);
    float4 hv = *(const float4*)(h + n * 128 + lane * 4);
    float4 acc = make_float4(hv.x * aw, hv.y * aw, hv.z * aw, hv.w * aw);
    #pragma unroll 2
    for (int e = beg; e < end; e++) {
        int s = __ldg(csr + e);
        float4 as = *(const float4*)(asrc + s * 4);
        float4 we = expsub4(lr4(add4(as, ad)), m);
        ssum = add4(ssum, we);
        float a = getc(we, hd);
        float4 hs = *(const float4*)(h + s * 128 + lane * 4);
        acc.x += hs.x * a; acc.y += hs.y * a; acc.z += hs.z * a; acc.w += hs.w * a;
    }

    float inv = 1.f / (getc(ssum, hd) + 1e-16f);
    int c = lane * 4;
    float4 bb = *(const float4*)(b_gat + c);
    float4 w1 = *(const float4*)(bn1w + c);
    float4 b1 = *(const float4*)(bn1b + c);
    float4 v;
    v.x = elu_f(acc.x * inv + bb.x) * w1.x + b1.x;
    v.y = elu_f(acc.y * inv + bb.y) * w1.y + b1.y;
    v.z = elu_f(acc.z * inv + bb.z) * w1.z + b1.z;
    v.w = elu_f(acc.w * inv + bb.w) * w1.w + b1.w;
    *(float4*)(out1 + n * 128 + c) = v;

    if (lane == 0) dinv[n] = rsqrtf((float)(end - beg + 1));
}

// ---------------- GCN aggregation + gate: warp per node ----------------
__global__ __launch_bounds__(256) void gcn_agg_kernel(const int* __restrict__ csr,
                                                      const int* __restrict__ offs,
                                                      const float* __restrict__ h2,
                                                      const float* __restrict__ dinv,
                                                      const float* __restrict__ b_gcn,
                                                      const float* __restrict__ bn2w,
                                                      const float* __restrict__ bn2b,
                                                      const float* __restrict__ W_gate,
                                                      const float* __restrict__ b_gate,
                                                      float* __restrict__ out2,
                                                      float* __restrict__ gate, int N) {
    int n = (blockIdx.x * 256 + threadIdx.x) >> 5;
    if (n >= N) return;
    int lane = threadIdx.x & 31;
    int beg = offs[n], end = offs[n + 1];
    float dn = dinv[n];

    float4 hv = *(const float4*)(h2 + n * 128 + lane * 4);
    float fs = dn * dn;
    float4 acc = make_float4(hv.x * fs, hv.y * fs, hv.z * fs, hv.w * fs);
    #pragma unroll 2
    for (int e = beg; e < end; e++) {
        int s = __ldg(csr + e);
        float f = dinv[s] * dn;
        float4 hs = *(const float4*)(h2 + s * 128 + lane * 4);
        acc.x += hs.x * f; acc.y += hs.y * f; acc.z += hs.z * f; acc.w += hs.w * f;
    }

    int c = lane * 4;
    float4 bb = *(const float4*)(b_gcn + c);
    float4 w2 = *(const float4*)(bn2w + c);
    float4 b2 = *(const float4*)(bn2b + c);
    float4 v;
    v.x = elu_f(acc.x + bb.x) * w2.x + b2.x;
    v.y = elu_f(acc.y + bb.y) * w2.y + b2.y;
    v.z = elu_f(acc.z + bb.z) * w2.z + b2.z;
    v.w = elu_f(acc.w + bb.w) * w2.w + b2.w;
    *(float4*)(out2 + n * 128 + c) = v;

    float4 wg = *(const float4*)(W_gate + c);
    float p = v.x * wg.x + v.y * wg.y + v.z * wg.z + v.w * wg.w;
    #pragma unroll
    for (int o = 16; o; o >>= 1) p += __shfl_xor_sync(0xffffffffu, p, o);
    if (lane == 0) gate[n] = p + b_gate[0];
}

// ---------------- pooling + FC: one block per graph, no atomics ----------------
__global__ __launch_bounds__(256) void pool_kernel(const float* __restrict__ out2,
                                                   const float* __restrict__ gate,
                                                   const int* __restrict__ gs,
                                                   const int* __restrict__ ge,
                                                   const float* __restrict__ W_fc,
                                                   const float* __restrict__ b_fc,
                                                   float* __restrict__ out) {
    int g = blockIdx.x;
    int start = gs[g], end = ge[g];
    int tid = threadIdx.x;
    __shared__ float red[256];
    __shared__ float wsh[256];

    // segment max of gate
    float mx = -3.4e38f;
    for (int n = start + tid; n < end; n += 256) mx = fmaxf(mx, gate[n]);
    red[tid] = mx;
    __syncthreads();
    #pragma unroll
    for (int o = 128; o; o >>= 1) {
        if (tid < o) red[tid] = fmaxf(red[tid], red[tid + o]);
        __syncthreads();
    }
    float gmax = red[0];
    __syncthreads();

    int c = tid & 127, half = tid >> 7;
    float acc = 0.f, wloc = 0.f;
    for (int t0 = start; t0 < end; t0 += 256) {
        int tc = min(256, end - t0);
        if (tid < tc) {
            float wv = __expf(gate[t0 + tid] - gmax);
            wsh[tid] = wv;
            wloc += wv;
        }
        __syncthreads();
        for (int j = half; j < tc; j += 2)
            acc += wsh[j] * out2[(t0 + j) * 128 + c];
        __syncthreads();
    }

    // reduce exp-sum
    red[tid] = wloc;
    __syncthreads();
    #pragma unroll
    for (int o = 128; o; o >>= 1) {
        if (tid < o) red[tid] += red[tid + o];
        __syncthreads();
    }
    float wsum = red[0];
    __syncthreads();

    // combine column halves, dot with W_fc
    red[tid] = acc;
    __syncthreads();
    float val = 0.f;
    if (tid < 128) val = (red[tid] + red[tid + 128]) / (wsum + 1e-16f) * W_fc[tid];
    __syncthreads();
    red[tid] = (tid < 128) ? val : 0.f;
    __syncthreads();
    #pragma unroll
    for (int o = 128; o; o >>= 1) {
        if (tid < o) red[tid] += red[tid + o];
        __syncthreads();
    }
    if (tid == 0) out[g] = red[0] + b_fc[0];
}

// ---------------- launch ----------------
extern "C" void kernel_launch(void* const* d_in, const int* in_sizes, int n_in,
                              void* d_out, int out_size) {
    const float* x       = (const float*)d_in[0];
    const int*   ei      = (const int*)d_in[1];
    const int*   batch   = (const int*)d_in[2];
    const float* W_gat   = (const float*)d_in[3];
    const float* att_src = (const float*)d_in[4];
    const float* att_dst = (const float*)d_in[5];
    const float* b_gat   = (const float*)d_in[6];
    const float* bn1w    = (const float*)d_in[7];
    const float* bn1b    = (const float*)d_in[8];
    const float* W_gcn   = (const float*)d_in[9];
    const float* b_gcn   = (const float*)d_in[10];
    const float* bn2w    = (const float*)d_in[11];
    const float* bn2b    = (const float*)d_in[12];
    const float* W_gate  = (const float*)d_in[13];
    const float* b_gate  = (const float*)d_in[14];
    const float* W_fc    = (const float*)d_in[15];
    const float* b_fc    = (const float*)d_in[16];
    float* out = (float*)d_out;

    int N = in_sizes[0] / 128;
    int E = in_sizes[1] / 2;

    float *p_h, *p_asrc, *p_adst, *p_out1, *p_h2, *p_out2, *p_gate, *p_dinv;
    int *p_cnt, *p_offs, *p_cursor, *p_csr, *p_gs, *p_ge;
    cudaGetSymbolAddress((void**)&p_h,     g_h);
    cudaGetSymbolAddress((void**)&p_asrc,  g_asrc);
    cudaGetSymbolAddress((void**)&p_adst,  g_adst);
    cudaGetSymbolAddress((void**)&p_out1,  g_out1);
    cudaGetSymbolAddress((void**)&p_h2,    g_h2);
    cudaGetSymbolAddress((void**)&p_out2,  g_out2);
    cudaGetSymbolAddress((void**)&p_gate,  g_gate);
    cudaGetSymbolAddress((void**)&p_dinv,  g_dinv);
    cudaGetSymbolAddress((void**)&p_cnt,   g_cnt);
    cudaGetSymbolAddress((void**)&p_offs,  g_offs);
    cudaGetSymbolAddress((void**)&p_cursor,g_cursor);
    cudaGetSymbolAddress((void**)&p_csr,   g_csr);
    cudaGetSymbolAddress((void**)&p_gs,    g_gstart);
    cudaGetSymbolAddress((void**)&p_ge,    g_gend);

    init_kernel<<<(N + 255) / 256, 256>>>(p_cnt, p_gs, p_ge, N);
    bounds_kernel<<<(N + 255) / 256, 256>>>(batch, p_gs, p_ge, N);

    // CSR build (by dst)
    hist_kernel<<<(E + 255) / 256, 256>>>(ei, E, p_cnt);
    scan_kernel<<<1, 1024>>>(p_cnt, p_offs, p_cursor, N, E);
    scatter_kernel<<<(E + 255) / 256, 256>>>(ei, E, p_cursor, p_csr);

    // GAT
    gemm128_kernel<<<(N + 127) / 128, 256>>>(x, W_gat, p_h, N);
    attn_kernel<<<(N * 4 + 255) / 256, 256>>>(p_h, att_src, att_dst, p_asrc, p_adst, N);
    gat_agg_kernel<<<(N * 32 + 255) / 256, 256>>>(p_csr, p_offs, p_h, p_asrc, p_adst,
                                                  b_gat, bn1w, bn1b, p_out1, p_dinv, N);

    // GCN
    gemm128_kernel<<<(N + 127) / 128, 256>>>(p_out1, W_gcn, p_h2, N);
    gcn_agg_kernel<<<(N * 32 + 255) / 256, 256>>>(p_csr, p_offs, p_h2, p_dinv,
                                                  b_gcn, bn2w, bn2b, W_gate, b_gate,
                                                  p_out2, p_gate, N);

    // pooling + FC
    pool_kernel<<<64, 256>>>(p_out2, p_gate, p_gs, p_ge, W_fc, b_fc, out);
}

// round 3
// speedup vs baseline: 2.9391x; 1.3651x over previous
#include <cuda_runtime.h>
#include <math.h>

#define NMAX 50048
#define EMAX 800000
#define SCAN_B 256

// ---------------- scratch (device globals) ----------------
__device__ float g_h[NMAX * 128];      // x @ W_gat
__device__ float g_asrc[NMAX * 4];
__device__ float g_adst[NMAX * 4];
__device__ float g_out1[NMAX * 128];
__device__ float g_h2[NMAX * 128];
__device__ float g_out2[NMAX * 128];
__device__ float g_gate[NMAX];
__device__ float g_dinv[NMAX];
__device__ int   g_cnt[NMAX];
__device__ int   g_offs[NMAX + 1];
__device__ int   g_cursor[NMAX];
__device__ int   g_csr[EMAX];
__device__ int   g_bsum[(NMAX + SCAN_B - 1) / SCAN_B];
__device__ int   g_boff[(NMAX + SCAN_B - 1) / SCAN_B];
__device__ int   g_gstart[64];
__device__ int   g_gend[64];

// ---------------- helpers ----------------
__device__ __forceinline__ float lrelu(float v) { return v > 0.f ? v : 0.2f * v; }
__device__ __forceinline__ float elu_f(float v) { return v > 0.f ? v : (__expf(v) - 1.f); }
__device__ __forceinline__ float getc(float4 v, int i) {
    return i == 0 ? v.x : i == 1 ? v.y : i == 2 ? v.z : v.w;
}
__device__ __forceinline__ void ffma2(unsigned long long& d, unsigned long long a,
                                      unsigned long long b) {
    asm("fma.rn.f32x2 %0, %1, %2, %0;" : "+l"(d) : "l"(a), "l"(b));
}
__device__ __forceinline__ unsigned long long dup2(float v) {
    unsigned long long r;
    asm("mov.b64 %0, {%1, %1};" : "=l"(r) : "f"(v));
    return r;
}

// ---------------- init ----------------
__global__ void init_kernel(int* cnt, int* gs, int* ge, int N) {
    int i = blockIdx.x * blockDim.x + threadIdx.x;
    if (i < N) cnt[i] = 0;
    if (i < 64) { gs[i] = 0; ge[i] = 0; }
}

// ---------------- GEMM: C[N,128] = A[N,128] @ W[128,128] (+ optional attn epilogue) ----------------
template <bool ATTN>
__global__ __launch_bounds__(256) void gemm128_kernel(const float* __restrict__ A,
                                                      const float* __restrict__ W,
                                                      float* __restrict__ C,
                                                      const float* __restrict__ att_src,
                                                      const float* __restrict__ att_dst,
                                                      float* __restrict__ asrc,
                                                      float* __restrict__ adst, int N) {
    __shared__ float Ws[32 * 128];
    int t  = threadIdx.x;
    int cg = t & 7;
    int rq = t >> 3;
    int row0 = blockIdx.x * 128 + rq * 4;

    unsigned long long acc[4][8];
    #pragma unroll
    for (int j = 0; j < 4; j++)
        #pragma unroll
        for (int i = 0; i < 8; i++) acc[j][i] = 0ull;

    #pragma unroll
    for (int kk = 0; kk < 128; kk += 32) {
        __syncthreads();
        #pragma unroll
        for (int i = t; i < 1024; i += 256)
            ((float4*)Ws)[i] = ((const float4*)W)[kk * 32 + i];
        __syncthreads();

        #pragma unroll
        for (int k4 = 0; k4 < 8; k4++) {
            float4 a[4];
            #pragma unroll
            for (int j = 0; j < 4; j++) {
                int row = row0 + j;
                a[j] = (row < N) ? ((const float4*)A)[row * 32 + (kk >> 2) + k4]
                                 : make_float4(0.f, 0.f, 0.f, 0.f);
            }
            #pragma unroll
            for (int u = 0; u < 4; u++) {
                const float* wr = Ws + (k4 * 4 + u) * 128 + cg * 16;
                ulonglong2 w0 = *(const ulonglong2*)(wr);
                ulonglong2 w1 = *(const ulonglong2*)(wr + 4);
                ulonglong2 w2 = *(const ulonglong2*)(wr + 8);
                ulonglong2 w3 = *(const ulonglong2*)(wr + 12);
                #pragma unroll
                for (int j = 0; j < 4; j++) {
                    unsigned long long av2 = dup2(getc(a[j], u));
                    ffma2(acc[j][0], av2, w0.x); ffma2(acc[j][1], av2, w0.y);
                    ffma2(acc[j][2], av2, w1.x); ffma2(acc[j][3], av2, w1.y);
                    ffma2(acc[j][4], av2, w2.x); ffma2(acc[j][5], av2, w2.y);
                    ffma2(acc[j][6], av2, w3.x); ffma2(acc[j][7], av2, w3.y);
                }
            }
        }
    }

    float cf[4][16];
    #pragma unroll
    for (int j = 0; j < 4; j++)
        #pragma unroll
        for (int m = 0; m < 4; m++) {
            float2 lo = *(float2*)&acc[j][2 * m];
            float2 hi = *(float2*)&acc[j][2 * m + 1];
            cf[j][m * 4 + 0] = lo.x; cf[j][m * 4 + 1] = lo.y;
            cf[j][m * 4 + 2] = hi.x; cf[j][m * 4 + 3] = hi.y;
        }

    #pragma unroll
    for (int j = 0; j < 4; j++) {
        int row = row0 + j;
        if (row < N) {
            float4* cp = (float4*)(C + row * 128 + cg * 16);
            #pragma unroll
            for (int m = 0; m < 4; m++)
                cp[m] = make_float4(cf[j][m * 4], cf[j][m * 4 + 1],
                                    cf[j][m * 4 + 2], cf[j][m * 4 + 3]);
        }
    }

    if (ATTN) {
        // head for this thread's 16 cols: hg = cg>>1; within-head offset (cg&1)*16
        int hg = cg >> 1;
        const float* as_p = att_src + hg * 32 + (cg & 1) * 16;
        const float* ad_p = att_dst + hg * 32 + (cg & 1) * 16;
        float av[16], dv[16];
        #pragma unroll
        for (int k = 0; k < 16; k++) { av[k] = as_p[k]; dv[k] = ad_p[k]; }
        #pragma unroll
        for (int j = 0; j < 4; j++) {
            float ps = 0.f, pd = 0.f;
            #pragma unroll
            for (int k = 0; k < 16; k++) { ps += cf[j][k] * av[k]; pd += cf[j][k] * dv[k]; }
            ps += __shfl_xor_sync(0xffffffffu, ps, 1);
            pd += __shfl_xor_sync(0xffffffffu, pd, 1);
            int row = row0 + j;
            if (!(cg & 1) && row < N) {
                asrc[row * 4 + hg] = ps;
                adst[row * 4 + hg] = pd;
            }
        }
    }
}

// ---------------- CSR build ----------------
__global__ void hist_kernel(const int* __restrict__ ei, int E, int* cnt) {
    int e = blockIdx.x * blockDim.x + threadIdx.x;
    if (e >= E) return;
    atomicAdd(cnt + ei[E + e], 1);
}

// phase A: per-block sums
__global__ __launch_bounds__(SCAN_B) void blocksum_kernel(const int* __restrict__ cnt,
                                                          int* bsum, int N) {
    __shared__ int sh[SCAN_B];
    int i = blockIdx.x * SCAN_B + threadIdx.x;
    sh[threadIdx.x] = (i < N) ? cnt[i] : 0;
    __syncthreads();
    #pragma unroll
    for (int o = SCAN_B / 2; o; o >>= 1) {
        if (threadIdx.x < o) sh[threadIdx.x] += sh[threadIdx.x + o];
        __syncthreads();
    }
    if (threadIdx.x == 0) bsum[blockIdx.x] = sh[0];
}

// phase B: exclusive scan of block sums (1 block)
__global__ __launch_bounds__(256) void bscan_kernel(const int* __restrict__ bsum,
                                                    int* boff, int NB) {
    __shared__ int sh[256];
    int t = threadIdx.x;
    sh[t] = (t < NB) ? bsum[t] : 0;
    __syncthreads();
    #pragma unroll
    for (int o = 1; o < 256; o <<= 1) {
        int v = (t >= o) ? sh[t - o] : 0;
        __syncthreads();
        sh[t] += v;
        __syncthreads();
    }
    if (t < NB) boff[t] = (t == 0) ? 0 : sh[t - 1];
}

// phase C: intra-block exclusive scan + block offset
__global__ __launch_bounds__(SCAN_B) void scanfin_kernel(const int* __restrict__ cnt,
                                                         const int* __restrict__ boff,
                                                         int* offs, int* cursor, int N, int E) {
    __shared__ int sh[SCAN_B];
    int t = threadIdx.x;
    int i = blockIdx.x * SCAN_B + t;
    int v = (i < N) ? cnt[i] : 0;
    sh[t] = v;
    __syncthreads();
    #pragma unroll
    for (int o = 1; o < SCAN_B; o <<= 1) {
        int u = (t >= o) ? sh[t - o] : 0;
        __syncthreads();
        sh[t] += u;
        __syncthreads();
    }
    if (i < N) {
        int off = boff[blockIdx.x] + sh[t] - v;   // exclusive
        offs[i] = off;
        cursor[i] = off;
    }
    if (i == 0) offs[N] = E;
}

__global__ void scatter_kernel(const int* __restrict__ ei, int E, int* cursor, int* csr) {
    int e = blockIdx.x * blockDim.x + threadIdx.x;
    if (e >= E) return;
    int d = ei[E + e];
    int pos = atomicAdd(cursor + d, 1);
    csr[pos] = ei[e];
}

// ---------------- graph boundaries ----------------
__global__ void bounds_kernel(const int* __restrict__ batch, int* gs, int* ge, int N) {
    int n = blockIdx.x * blockDim.x + threadIdx.x;
    if (n >= N) return;
    int b = batch[n];
    if (n == 0 || batch[n - 1] != b) gs[b] = n;
    if (n == N - 1 || batch[n + 1] != b) ge[b] = n + 1;
}

// ---------------- GAT aggregation: warp/node, single-pass softmax, lane-parallel exp ----------------
__global__ __launch_bounds__(256) void gat_agg_kernel(const int* __restrict__ csr,
                                                      const int* __restrict__ offs,
                                                      const float* __restrict__ h,
                                                      const float* __restrict__ asrc,
                                                      const float* __restrict__ adst,
                                                      const float* __restrict__ b_gat,
                                                      const float* __restrict__ bn1w,
                                                      const float* __restrict__ bn1b,
                                                      float* __restrict__ out1,
                                                      float* __restrict__ dinv, int N) {
    int n = (blockIdx.x * 256 + threadIdx.x) >> 5;
    if (n >= N) return;
    int lane = threadIdx.x & 31;
    int hd  = lane >> 3;        // head 0..3
    int sub = lane & 7;         // edge slot 0..7
    int grp = lane & 24;        // (hd*8)
    int beg = offs[n], end = offs[n + 1];

    float adn = __ldg(adst + n * 4 + hd);
    float asn = __ldg(asrc + n * 4 + hd);
    float wself = __expf(lrelu(asn + adn));

    // self contribution
    float4 hv = *(const float4*)(h + n * 128 + lane * 4);
    float4 acc = make_float4(hv.x * wself, hv.y * wself, hv.z * wself, hv.w * wself);

    float wpart = 0.f;  // per-lane partial exp-sum for head hd (over its edge slots)
    for (int c0 = beg; c0 < end; c0 += 8) {
        int e = c0 + sub;
        float w = 0.f; int s = 0;
        if (e < end) {
            s = __ldg(csr + e);
            w = __expf(lrelu(__ldg(asrc + s * 4 + hd) + adn));
        }
        wpart += w;
        int cnt = min(8, end - c0);
        for (int i = 0; i < cnt; i++) {
            int   si = __shfl_sync(0xffffffffu, s, i);
            float a  = __shfl_sync(0xffffffffu, w, grp + i);
            float4 hs = *(const float4*)(h + si * 128 + lane * 4);
            acc.x += hs.x * a; acc.y += hs.y * a; acc.z += hs.z * a; acc.w += hs.w * a;
        }
    }

    // reduce exp-sum within the 8-lane head group
    #pragma unroll
    for (int o = 1; o < 8; o <<= 1) wpart += __shfl_xor_sync(0xffffffffu, wpart, o);
    float inv = 1.f / (wpart + wself + 1e-16f);

    int c = lane * 4;
    float4 bb = *(const float4*)(b_gat + c);
    float4 w1 = *(const float4*)(bn1w + c);
    float4 b1 = *(const float4*)(bn1b + c);
    float4 v;
    v.x = elu_f(acc.x * inv + bb.x) * w1.x + b1.x;
    v.y = elu_f(acc.y * inv + bb.y) * w1.y + b1.y;
    v.z = elu_f(acc.z * inv + bb.z) * w1.z + b1.z;
    v.w = elu_f(acc.w * inv + bb.w) * w1.w + b1.w;
    *(float4*)(out1 + n * 128 + c) = v;

    if (lane == 0) dinv[n] = rsqrtf((float)(end - beg + 1));
}

// ---------------- GCN aggregation + gate ----------------
__global__ __launch_bounds__(256) void gcn_agg_kernel(const int* __restrict__ csr,
                                                      const int* __restrict__ offs,
                                                      const float* __restrict__ h2,
                                                      const float* __restrict__ dinv,
                                                      const float* __restrict__ b_gcn,
                                                      const float* __restrict__ bn2w,
                                                      const float* __restrict__ bn2b,
                                                      const float* __restrict__ W_gate,
                                                      const float* __restrict__ b_gate,
                                                      float* __restrict__ out2,
                                                      float* __restrict__ gate, int N) {
    int n = (blockIdx.x * 256 + threadIdx.x) >> 5;
    if (n >= N) return;
    int lane = threadIdx.x & 31;
    int sub = lane & 7;
    int beg = offs[n], end = offs[n + 1];
    float dn = __ldg(dinv + n);

    float4 hv = *(const float4*)(h2 + n * 128 + lane * 4);
    float fs = dn * dn;
    float4 acc = make_float4(hv.x * fs, hv.y * fs, hv.z * fs, hv.w * fs);

    for (int c0 = beg; c0 < end; c0 += 8) {
        int e = c0 + sub;
        float f = 0.f; int s = 0;
        if (e < end) {
            s = __ldg(csr + e);
            f = __ldg(dinv + s) * dn;
        }
        int cnt = min(8, end - c0);
        for (int i = 0; i < cnt; i++) {
            int   si = __shfl_sync(0xffffffffu, s, i);
            float a  = __shfl_sync(0xffffffffu, f, i);
            float4 hs = *(const float4*)(h2 + si * 128 + lane * 4);
            acc.x += hs.x * a; acc.y += hs.y * a; acc.z += hs.z * a; acc.w += hs.w * a;
        }
    }

    int c = lane * 4;
    float4 bb = *(const float4*)(b_gcn + c);
    float4 w2 = *(const float4*)(bn2w + c);
    float4 b2 = *(const float4*)(bn2b + c);
    float4 v;
    v.x = elu_f(acc.x + bb.x) * w2.x + b2.x;
    v.y = elu_f(acc.y + bb.y) * w2.y + b2.y;
    v.z = elu_f(acc.z + bb.z) * w2.z + b2.z;
    v.w = elu_f(acc.w + bb.w) * w2.w + b2.w;
    *(float4*)(out2 + n * 128 + c) = v;

    float4 wg = *(const float4*)(W_gate + c);
    float p = v.x * wg.x + v.y * wg.y + v.z * wg.z + v.w * wg.w;
    #pragma unroll
    for (int o = 16; o; o >>= 1) p += __shfl_xor_sync(0xffffffffu, p, o);
    if (lane == 0) gate[n] = p + b_gate[0];
}

// ---------------- pooling + FC ----------------
__global__ __launch_bounds__(256) void pool_kernel(const float* __restrict__ out2,
                                                   const float* __restrict__ gate,
                                                   const int* __restrict__ gs,
                                                   const int* __restrict__ ge,
                                                   const float* __restrict__ W_fc,
                                                   const float* __restrict__ b_fc,
                                                   float* __restrict__ out) {
    int g = blockIdx.x;
    int start = gs[g], end = ge[g];
    int tid = threadIdx.x;
    __shared__ float red[256];
    __shared__ float wsh[256];

    float mx = -3.4e38f;
    for (int n = start + tid; n < end; n += 256) mx = fmaxf(mx, gate[n]);
    red[tid] = mx;
    __syncthreads();
    #pragma unroll
    for (int o = 128; o; o >>= 1) {
        if (tid < o) red[tid] = fmaxf(red[tid], red[tid + o]);
        __syncthreads();
    }
    float gmax = red[0];
    __syncthreads();

    int c = tid & 127, half = tid >> 7;
    float acc = 0.f, wloc = 0.f;
    for (int t0 = start; t0 < end; t0 += 256) {
        int tc = min(256, end - t0);
        if (tid < tc) {
            float wv = __expf(gate[t0 + tid] - gmax);
            wsh[tid] = wv;
            wloc += wv;
        }
        __syncthreads();
        for (int j = half; j < tc; j += 2)
            acc += wsh[j] * out2[(t0 + j) * 128 + c];
        __syncthreads();
    }

    red[tid] = wloc;
    __syncthreads();
    #pragma unroll
    for (int o = 128; o; o >>= 1) {
        if (tid < o) red[tid] += red[tid + o];
        __syncthreads();
    }
    float wsum = red[0];
    __syncthreads();

    red[tid] = acc;
    __syncthreads();
    float val = 0.f;
    if (tid < 128) val = (red[tid] + red[tid + 128]) / (wsum + 1e-16f) * W_fc[tid];
    __syncthreads();
    red[tid] = (tid < 128) ? val : 0.f;
    __syncthreads();
    #pragma unroll
    for (int o = 128; o; o >>= 1) {
        if (tid < o) red[tid] += red[tid + o];
        __syncthreads();
    }
    if (tid == 0) out[g] = red[0] + b_fc[0];
}

// ---------------- launch ----------------
extern "C" void kernel_launch(void* const* d_in, const int* in_sizes, int n_in,
                              void* d_out, int out_size) {
    const float* x       = (const float*)d_in[0];
    const int*   ei      = (const int*)d_in[1];
    const int*   batch   = (const int*)d_in[2];
    const float* W_gat   = (const float*)d_in[3];
    const float* att_src = (const float*)d_in[4];
    const float* att_dst = (const float*)d_in[5];
    const float* b_gat   = (const float*)d_in[6];
    const float* bn1w    = (const float*)d_in[7];
    const float* bn1b    = (const float*)d_in[8];
    const float* W_gcn   = (const float*)d_in[9];
    const float* b_gcn   = (const float*)d_in[10];
    const float* bn2w    = (const float*)d_in[11];
    const float* bn2b    = (const float*)d_in[12];
    const float* W_gate  = (const float*)d_in[13];
    const float* b_gate  = (const float*)d_in[14];
    const float* W_fc    = (const float*)d_in[15];
    const float* b_fc    = (const float*)d_in[16];
    float* out = (float*)d_out;

    int N = in_sizes[0] / 128;
    int E = in_sizes[1] / 2;
    int NB = (N + SCAN_B - 1) / SCAN_B;

    float *p_h, *p_asrc, *p_adst, *p_out1, *p_h2, *p_out2, *p_gate, *p_dinv;
    int *p_cnt, *p_offs, *p_cursor, *p_csr, *p_bsum, *p_boff, *p_gs, *p_ge;
    cudaGetSymbolAddress((void**)&p_h,     g_h);
    cudaGetSymbolAddress((void**)&p_asrc,  g_asrc);
    cudaGetSymbolAddress((void**)&p_adst,  g_adst);
    cudaGetSymbolAddress((void**)&p_out1,  g_out1);
    cudaGetSymbolAddress((void**)&p_h2,    g_h2);
    cudaGetSymbolAddress((void**)&p_out2,  g_out2);
    cudaGetSymbolAddress((void**)&p_gate,  g_gate);
    cudaGetSymbolAddress((void**)&p_dinv,  g_dinv);
    cudaGetSymbolAddress((void**)&p_cnt,   g_cnt);
    cudaGetSymbolAddress((void**)&p_offs,  g_offs);
    cudaGetSymbolAddress((void**)&p_cursor,g_cursor);
    cudaGetSymbolAddress((void**)&p_csr,   g_csr);
    cudaGetSymbolAddress((void**)&p_bsum,  g_bsum);
    cudaGetSymbolAddress((void**)&p_boff,  g_boff);
    cudaGetSymbolAddress((void**)&p_gs,    g_gstart);
    cudaGetSymbolAddress((void**)&p_ge,    g_gend);

    init_kernel<<<(N + 255) / 256, 256>>>(p_cnt, p_gs, p_ge, N);
    bounds_kernel<<<(N + 255) / 256, 256>>>(batch, p_gs, p_ge, N);

    // CSR build (by dst) with parallel scan
    hist_kernel<<<(E + 255) / 256, 256>>>(ei, E, p_cnt);
    blocksum_kernel<<<NB, SCAN_B>>>(p_cnt, p_bsum, N);
    bscan_kernel<<<1, 256>>>(p_bsum, p_boff, NB);
    scanfin_kernel<<<NB, SCAN_B>>>(p_cnt, p_boff, p_offs, p_cursor, N, E);
    scatter_kernel<<<(E + 255) / 256, 256>>>(ei, E, p_cursor, p_csr);

    // GAT (GEMM with fused attn-coefficient epilogue)
    gemm128_kernel<true><<<(N + 127) / 128, 256>>>(x, W_gat, p_h, att_src, att_dst,
                                                   p_asrc, p_adst, N);
    gat_agg_kernel<<<(N * 32 + 255) / 256, 256>>>(p_csr, p_offs, p_h, p_asrc, p_adst,
                                                  b_gat, bn1w, bn1b, p_out1, p_dinv, N);

    // GCN
    gemm128_kernel<false><<<(N + 127) / 128, 256>>>(p_out1, W_gcn, p_h2,
                                                    nullptr, nullptr, nullptr, nullptr, N);
    gcn_agg_kernel<<<(N * 32 + 255) / 256, 256>>>(p_csr, p_offs, p_h2, p_dinv,
                                                  b_gcn, bn2w, bn2b, W_gate, b_gate,
                                                  p_out2, p_gate, N);

    // pooling + FC
    pool_kernel<<<64, 256>>>(p_out2, p_gate, p_gs, p_ge, W_fc, b_fc, out);
}